// round 16
// baseline (speedup 1.0000x reference)
#include <cuda_runtime.h>
#include <cuda_fp16.h>
#include <cuda_bf16.h>

#define BATCH   2
#define CH      256
#define FH      96
#define FW      96
#define FHW     (FH * FW)
#define POOLED  7
#define NBINS   (POOLED * POOLED)
#define N_ROIS  512
#define SPATIAL_SCALE 0.0625f
#define TRANS_STD     0.1f

#define CH_HALF 128
#define HALF_BYTES (CH_HALF * 2)      // byte offset between channel halves
#define ROW_BYTES_H (FW * CH * 2)
#define COL_BYTES_H (CH * 2)

// NHWC fp16 scratch copy of the feature map: 9.4 MB (L2-resident)
__device__ __align__(128) __half g_feat_h[BATCH * FHW * CH];

__device__ __forceinline__ __half2 u2h(unsigned int u) { return *(__half2*)&u; }
__device__ __forceinline__ unsigned int h2u(__half2 h) { return *(unsigned int*)&h; }

// Guaranteed single LDG.64 (ptxas cannot split a v2 asm load).
__device__ __forceinline__ uint2 ldg64cs(const void* p) {
    uint2 v;
    asm("ld.global.nc.v2.u32 {%0, %1}, [%2];" : "=r"(v.x), "=r"(v.y) : "l"(p));
    return v;
}

// ---------------------------------------------------------------------------
// Transpose NCHW f32 -> NHWC f16 via 32x32 shared tiles.
// ---------------------------------------------------------------------------
__global__ __launch_bounds__(256) void nchw_to_nhwc_half_kernel(const float* __restrict__ in) {
    __shared__ float tile[32][33];
    const int b   = blockIdx.z;
    const int hw0 = blockIdx.x * 32;
    const int c0  = blockIdx.y * 32;

    const float* src = in + (size_t)b * CH * FHW;
    #pragma unroll
    for (int j = 0; j < 32; j += 8) {
        tile[threadIdx.y + j][threadIdx.x] =
            src[(size_t)(c0 + threadIdx.y + j) * FHW + hw0 + threadIdx.x];
    }
    __syncthreads();

    const int lane = threadIdx.y * 32 + threadIdx.x;
    const int cp   = lane & 15;
    const int hr   = lane >> 4;
    __half2* dst2 = (__half2*)g_feat_h + (size_t)b * FHW * (CH / 2);
    #pragma unroll
    for (int s = 0; s < 2; s++) {
        const int hl = hr + s * 16;
        const float a  = tile[2 * cp][hl];
        const float bv = tile[2 * cp + 1][hl];
        dst2[(size_t)(hw0 + hl) * (CH / 2) + (c0 >> 1) + cp] = __floats2half2_rn(a, bv);
    }
}

// ---------------------------------------------------------------------------
// Deformable PS-RoI pooling, v16: warp = bin x BOTH channel halves.
// Grid (7, 512): blockIdx.x = bin group. 224 threads = 7 warps, warp = bin.
// Same coordinates serve both halves (+256B pointer offset): 32 independent
// LDG.64 per lane -> 2x MLP at zero extra coordinate cost.
// ---------------------------------------------------------------------------

__global__ __launch_bounds__(224) void dpsroi_pool_kernel(
    const float* __restrict__ rois,     // [N_ROIS, 5]
    const float* __restrict__ trans,    // [N_ROIS, 2, 7, 7]
    float* __restrict__ out)            // [N_ROIS, CH, 7, 7]
{
    __shared__ float4 s_out4[7 * 66];         // [bin][66 float4] = 7.4 KB
    __shared__ int4   s_row[7];               // 4 row byte-offsets per bin
    __shared__ int4   s_col[7];               // 4 col byte-offsets per bin
    __shared__ uint4  s_axh[7];               // 4 half2-broadcast x weights
    __shared__ float4 s_ay[7];                // y weights * inv(count)

    const int grp  = blockIdx.x;              // bin group (7 bins)
    const int n    = blockIdx.y;
    const int tid  = threadIdx.x;
    const int cg   = tid & 31;
    const int bsub = tid >> 5;                // warp id = bin within group
    const int bin0 = grp * 7;

    const float* roi = rois + n * 5;
    const int   bidx = (int)roi[0];

    // ---------------- Phase 1: per-bin tables ----------------
    if (tid < 7) {
        const float x1 = rintf(roi[1]) * SPATIAL_SCALE - 0.5f;
        const float y1 = rintf(roi[2]) * SPATIAL_SCALE - 0.5f;
        const float x2 = (rintf(roi[3]) + 1.0f) * SPATIAL_SCALE - 0.5f;
        const float y2 = (rintf(roi[4]) + 1.0f) * SPATIAL_SCALE - 0.5f;
        const float rw = fmaxf(x2 - x1, 0.1f);
        const float rh = fmaxf(y2 - y1, 0.1f);
        const float bin_w = rw * (1.0f / POOLED);
        const float bin_h = rh * (1.0f / POOLED);
        const float sub_w = bin_w * 0.5f;
        const float sub_h = bin_h * 0.5f;

        const int bin = bin0 + tid;
        const int ph = bin / POOLED;
        const int pw = bin - ph * POOLED;

        const float tx = __ldg(trans + (size_t)n * 2 * NBINS + bin) * TRANS_STD;
        const float ty = __ldg(trans + (size_t)n * 2 * NBINS + NBINS + bin) * TRANS_STD;

        const float wstart = (float)pw * bin_w + x1 + tx * rw;
        const float hstart = (float)ph * bin_h + y1 + ty * rh;

        const float w0 = wstart, w1 = wstart + sub_w;
        const float h0 = hstart, h1 = hstart + sub_h;

        const float vx0 = (w0 >= -0.5f && w0 <= (float)FW - 0.5f) ? 1.0f : 0.0f;
        const float vx1 = (w1 >= -0.5f && w1 <= (float)FW - 0.5f) ? 1.0f : 0.0f;
        const float vy0 = (h0 >= -0.5f && h0 <= (float)FH - 0.5f) ? 1.0f : 0.0f;
        const float vy1 = (h1 >= -0.5f && h1 <= (float)FH - 0.5f) ? 1.0f : 0.0f;

        const float wc0 = fminf(fmaxf(w0, 0.0f), (float)FW - 1.0f);
        const float wc1 = fminf(fmaxf(w1, 0.0f), (float)FW - 1.0f);
        const float hc0 = fminf(fmaxf(h0, 0.0f), (float)FH - 1.0f);
        const float hc1 = fminf(fmaxf(h1, 0.0f), (float)FH - 1.0f);

        const float fx0 = floorf(wc0), fx1 = floorf(wc1);
        const float fy0 = floorf(hc0), fy1 = floorf(hc1);
        const float dx0 = wc0 - fx0, dx1 = wc1 - fx1;
        const float dy0 = hc0 - fy0, dy1 = hc1 - fy1;

        int4 col, row;
        col.x = (int)fx0 * COL_BYTES_H;
        col.y = (int)ceilf(wc0) * COL_BYTES_H;
        col.z = (int)fx1 * COL_BYTES_H;
        col.w = (int)ceilf(wc1) * COL_BYTES_H;
        row.x = (int)fy0 * ROW_BYTES_H;
        row.y = (int)ceilf(hc0) * ROW_BYTES_H;
        row.z = (int)fy1 * ROW_BYTES_H;
        row.w = (int)ceilf(hc1) * ROW_BYTES_H;

        const float count = (vx0 + vx1) * (vy0 + vy1);
        const float inv = (count > 0.0f) ? (1.0f / count) : 0.0f;

        uint4 axh;
        axh.x = h2u(__float2half2_rn(vx0 * (1.0f - dx0)));
        axh.y = h2u(__float2half2_rn(vx0 * dx0));
        axh.z = h2u(__float2half2_rn(vx1 * (1.0f - dx1)));
        axh.w = h2u(__float2half2_rn(vx1 * dx1));

        float4 ay;
        ay.x = vy0 * (1.0f - dy0) * inv;  ay.y = vy0 * dy0 * inv;
        ay.z = vy1 * (1.0f - dy1) * inv;  ay.w = vy1 * dy1 * inv;

        s_col[tid] = col;  s_row[tid] = row;
        s_axh[tid] = axh;  s_ay[tid]  = ay;
    }
    __syncthreads();

    // ---------------- Phase 2: one bin per warp, both halves ----------------
    const char* __restrict__ featb =
        (const char*)(g_feat_h + (size_t)bidx * FHW * CH) + cg * 8;

    {
        const int4   row = s_row[bsub];        // broadcast LDS.128
        const int4   col = s_col[bsub];
        const uint4  axh = s_axh[bsub];
        const float4 ay  = s_ay[bsub];
        const int   rowv[4] = {row.x, row.y, row.z, row.w};
        const float ayv[4]  = {ay.x, ay.y, ay.z, ay.w};
        const __half2 aw0 = u2h(axh.x), aw1 = u2h(axh.y);
        const __half2 aw2 = u2h(axh.z), aw3 = u2h(axh.w);

        float4 accA = make_float4(0.f, 0.f, 0.f, 0.f);  // half 0
        float4 accB = make_float4(0.f, 0.f, 0.f, 0.f);  // half 1
        #pragma unroll
        for (int r = 0; r < 4; r++) {
            const char* br = featb + rowv[r];
            // half 0
            const uint2 a0 = ldg64cs(br + col.x);
            const uint2 a1 = ldg64cs(br + col.y);
            const uint2 a2 = ldg64cs(br + col.z);
            const uint2 a3 = ldg64cs(br + col.w);
            // half 1 (+256B)
            const uint2 b0 = ldg64cs(br + col.x + HALF_BYTES);
            const uint2 b1 = ldg64cs(br + col.y + HALF_BYTES);
            const uint2 b2 = ldg64cs(br + col.z + HALF_BYTES);
            const uint2 b3 = ldg64cs(br + col.w + HALF_BYTES);

            __half2 ra0 = __hmul2(aw0, u2h(a0.x));
            __half2 ra1 = __hmul2(aw0, u2h(a0.y));
            ra0 = __hfma2(aw1, u2h(a1.x), ra0);
            ra1 = __hfma2(aw1, u2h(a1.y), ra1);
            ra0 = __hfma2(aw2, u2h(a2.x), ra0);
            ra1 = __hfma2(aw2, u2h(a2.y), ra1);
            ra0 = __hfma2(aw3, u2h(a3.x), ra0);
            ra1 = __hfma2(aw3, u2h(a3.y), ra1);

            __half2 rb0 = __hmul2(aw0, u2h(b0.x));
            __half2 rb1 = __hmul2(aw0, u2h(b0.y));
            rb0 = __hfma2(aw1, u2h(b1.x), rb0);
            rb1 = __hfma2(aw1, u2h(b1.y), rb1);
            rb0 = __hfma2(aw2, u2h(b2.x), rb0);
            rb1 = __hfma2(aw2, u2h(b2.y), rb1);
            rb0 = __hfma2(aw3, u2h(b3.x), rb0);
            rb1 = __hfma2(aw3, u2h(b3.y), rb1);

            const float2 la0 = __half22float2(ra0);
            const float2 ha0 = __half22float2(ra1);
            accA.x += ayv[r] * la0.x;
            accA.y += ayv[r] * la0.y;
            accA.z += ayv[r] * ha0.x;
            accA.w += ayv[r] * ha0.y;

            const float2 lb0 = __half22float2(rb0);
            const float2 hb0 = __half22float2(rb1);
            accB.x += ayv[r] * lb0.x;
            accB.y += ayv[r] * lb0.y;
            accB.z += ayv[r] * hb0.x;
            accB.w += ayv[r] * hb0.y;
        }

        // conflict-free STS.128: [bin][ch4], stride 66 float4
        s_out4[bsub * 66 + cg]      = accA;
        s_out4[bsub * 66 + 32 + cg] = accB;
    }

    __syncthreads();

    // ---------------- Phase 3: grouped output store ----------------
    // out element (c, bin0+j) <- s_outf[j*264 + c]; runs of 7 floats.
    float* o = out + (size_t)n * CH * NBINS + bin0;
    const float* s_outf = (const float*)s_out4;
    #pragma unroll
    for (int i = tid; i < CH * 7; i += 224) {
        const int c = i / 7;
        const int j = i - c * 7;
        o[c * NBINS + j] = s_outf[j * 264 + c];
    }
}

extern "C" void kernel_launch(void* const* d_in, const int* in_sizes, int n_in,
                              void* d_out, int out_size)
{
    const float* bottom_data  = (const float*)d_in[0];  // (2,256,96,96)
    const float* bottom_rois  = (const float*)d_in[1];  // (512,5)
    const float* bottom_trans = (const float*)d_in[2];  // (512,2,7,7)
    float* out = (float*)d_out;                         // (512,256,7,7)

    {
        dim3 tb(32, 8);
        dim3 tg(FHW / 32, CH / 32, BATCH);
        nchw_to_nhwc_half_kernel<<<tg, tb>>>(bottom_data);
    }
    {
        dim3 pg(7, N_ROIS);
        dpsroi_pool_kernel<<<pg, 224>>>(bottom_rois, bottom_trans, out);
    }
}

// round 17
// speedup vs baseline: 1.0495x; 1.0495x over previous
#include <cuda_runtime.h>
#include <cuda_fp16.h>
#include <cuda_bf16.h>

#define BATCH   2
#define CH      256
#define FH      96
#define FW      96
#define FHW     (FH * FW)
#define POOLED  7
#define NBINS   (POOLED * POOLED)
#define N_ROIS  512
#define SPATIAL_SCALE 0.0625f
#define TRANS_STD     0.1f

#define ROW_BYTES_H (FW * CH * 2)
#define COL_BYTES_H (CH * 2)

// NHWC fp16 scratch copy of the feature map: 9.4 MB (L2-resident)
__device__ __align__(128) __half g_feat_h[BATCH * FHW * CH];

__device__ __forceinline__ __half2 u2h(unsigned int u) { return *(__half2*)&u; }
__device__ __forceinline__ unsigned int h2u(__half2 h) { return *(unsigned int*)&h; }

// Guaranteed single LDG.128 (ptxas cannot split a v4 asm load).
__device__ __forceinline__ uint4 ldg128cs(const void* p) {
    uint4 v;
    asm("ld.global.nc.v4.u32 {%0, %1, %2, %3}, [%4];"
        : "=r"(v.x), "=r"(v.y), "=r"(v.z), "=r"(v.w) : "l"(p));
    return v;
}

// ---------------------------------------------------------------------------
// Transpose NCHW f32 -> NHWC f16 via 32x32 shared tiles.
// ---------------------------------------------------------------------------
__global__ __launch_bounds__(256) void nchw_to_nhwc_half_kernel(const float* __restrict__ in) {
    __shared__ float tile[32][33];
    const int b   = blockIdx.z;
    const int hw0 = blockIdx.x * 32;
    const int c0  = blockIdx.y * 32;

    const float* src = in + (size_t)b * CH * FHW;
    #pragma unroll
    for (int j = 0; j < 32; j += 8) {
        tile[threadIdx.y + j][threadIdx.x] =
            src[(size_t)(c0 + threadIdx.y + j) * FHW + hw0 + threadIdx.x];
    }
    __syncthreads();

    const int lane = threadIdx.y * 32 + threadIdx.x;
    const int cp   = lane & 15;
    const int hr   = lane >> 4;
    __half2* dst2 = (__half2*)g_feat_h + (size_t)b * FHW * (CH / 2);
    #pragma unroll
    for (int s = 0; s < 2; s++) {
        const int hl = hr + s * 16;
        const float a  = tile[2 * cp][hl];
        const float bv = tile[2 * cp + 1][hl];
        dst2[(size_t)(hw0 + hl) * (CH / 2) + (c0 >> 1) + cp] = __floats2half2_rn(a, bv);
    }
}

// ---------------------------------------------------------------------------
// Deformable PS-RoI pooling, v17: warp = bin x ALL 256 channels, LDG.128.
// Grid (7, 512): blockIdx.x = bin group. 224 threads = 7 warps, warp = bin.
// Lane l owns 8 consecutive channels: each stencil position is ONE LDG.128
// (16 loads/lane total -- half of v16's 32 LDG.64 for identical work).
// HFMA2 column stage, f32 row combine, conflict-free staging, grouped store.
// ---------------------------------------------------------------------------

__global__ __launch_bounds__(224) void dpsroi_pool_kernel(
    const float* __restrict__ rois,     // [N_ROIS, 5]
    const float* __restrict__ trans,    // [N_ROIS, 2, 7, 7]
    float* __restrict__ out)            // [N_ROIS, CH, 7, 7]
{
    __shared__ float4 s_out4[7 * 66];         // [bin][66 float4] = 7.4 KB
    __shared__ int4   s_row[7];               // 4 row byte-offsets per bin
    __shared__ int4   s_col[7];               // 4 col byte-offsets per bin
    __shared__ uint4  s_axh[7];               // 4 half2-broadcast x weights
    __shared__ float4 s_ay[7];                // y weights * inv(count)

    const int grp  = blockIdx.x;              // bin group (7 bins)
    const int n    = blockIdx.y;
    const int tid  = threadIdx.x;
    const int cg   = tid & 31;                // lane: channels [8cg, 8cg+8)
    const int bsub = tid >> 5;                // warp id = bin within group
    const int bin0 = grp * 7;

    const float* roi = rois + n * 5;
    const int   bidx = (int)roi[0];

    // ---------------- Phase 1: per-bin tables ----------------
    if (tid < 7) {
        const float x1 = rintf(roi[1]) * SPATIAL_SCALE - 0.5f;
        const float y1 = rintf(roi[2]) * SPATIAL_SCALE - 0.5f;
        const float x2 = (rintf(roi[3]) + 1.0f) * SPATIAL_SCALE - 0.5f;
        const float y2 = (rintf(roi[4]) + 1.0f) * SPATIAL_SCALE - 0.5f;
        const float rw = fmaxf(x2 - x1, 0.1f);
        const float rh = fmaxf(y2 - y1, 0.1f);
        const float bin_w = rw * (1.0f / POOLED);
        const float bin_h = rh * (1.0f / POOLED);
        const float sub_w = bin_w * 0.5f;
        const float sub_h = bin_h * 0.5f;

        const int bin = bin0 + tid;
        const int ph = bin / POOLED;
        const int pw = bin - ph * POOLED;

        const float tx = __ldg(trans + (size_t)n * 2 * NBINS + bin) * TRANS_STD;
        const float ty = __ldg(trans + (size_t)n * 2 * NBINS + NBINS + bin) * TRANS_STD;

        const float wstart = (float)pw * bin_w + x1 + tx * rw;
        const float hstart = (float)ph * bin_h + y1 + ty * rh;

        const float w0 = wstart, w1 = wstart + sub_w;
        const float h0 = hstart, h1 = hstart + sub_h;

        const float vx0 = (w0 >= -0.5f && w0 <= (float)FW - 0.5f) ? 1.0f : 0.0f;
        const float vx1 = (w1 >= -0.5f && w1 <= (float)FW - 0.5f) ? 1.0f : 0.0f;
        const float vy0 = (h0 >= -0.5f && h0 <= (float)FH - 0.5f) ? 1.0f : 0.0f;
        const float vy1 = (h1 >= -0.5f && h1 <= (float)FH - 0.5f) ? 1.0f : 0.0f;

        const float wc0 = fminf(fmaxf(w0, 0.0f), (float)FW - 1.0f);
        const float wc1 = fminf(fmaxf(w1, 0.0f), (float)FW - 1.0f);
        const float hc0 = fminf(fmaxf(h0, 0.0f), (float)FH - 1.0f);
        const float hc1 = fminf(fmaxf(h1, 0.0f), (float)FH - 1.0f);

        const float fx0 = floorf(wc0), fx1 = floorf(wc1);
        const float fy0 = floorf(hc0), fy1 = floorf(hc1);
        const float dx0 = wc0 - fx0, dx1 = wc1 - fx1;
        const float dy0 = hc0 - fy0, dy1 = hc1 - fy1;

        int4 col, row;
        col.x = (int)fx0 * COL_BYTES_H;
        col.y = (int)ceilf(wc0) * COL_BYTES_H;
        col.z = (int)fx1 * COL_BYTES_H;
        col.w = (int)ceilf(wc1) * COL_BYTES_H;
        row.x = (int)fy0 * ROW_BYTES_H;
        row.y = (int)ceilf(hc0) * ROW_BYTES_H;
        row.z = (int)fy1 * ROW_BYTES_H;
        row.w = (int)ceilf(hc1) * ROW_BYTES_H;

        const float count = (vx0 + vx1) * (vy0 + vy1);
        const float inv = (count > 0.0f) ? (1.0f / count) : 0.0f;

        uint4 axh;
        axh.x = h2u(__float2half2_rn(vx0 * (1.0f - dx0)));
        axh.y = h2u(__float2half2_rn(vx0 * dx0));
        axh.z = h2u(__float2half2_rn(vx1 * (1.0f - dx1)));
        axh.w = h2u(__float2half2_rn(vx1 * dx1));

        float4 ay;
        ay.x = vy0 * (1.0f - dy0) * inv;  ay.y = vy0 * dy0 * inv;
        ay.z = vy1 * (1.0f - dy1) * inv;  ay.w = vy1 * dy1 * inv;

        s_col[tid] = col;  s_row[tid] = row;
        s_axh[tid] = axh;  s_ay[tid]  = ay;
    }
    __syncthreads();

    // ---------------- Phase 2: one bin per warp, 256 channels ----------------
    const char* __restrict__ featb =
        (const char*)(g_feat_h + (size_t)bidx * FHW * CH) + cg * 16;

    {
        const int4   row = s_row[bsub];        // broadcast LDS.128
        const int4   col = s_col[bsub];
        const uint4  axh = s_axh[bsub];
        const float4 ay  = s_ay[bsub];
        const int   rowv[4] = {row.x, row.y, row.z, row.w};
        const float ayv[4]  = {ay.x, ay.y, ay.z, ay.w};
        const __half2 aw0 = u2h(axh.x), aw1 = u2h(axh.y);
        const __half2 aw2 = u2h(axh.z), aw3 = u2h(axh.w);

        float4 accLo = make_float4(0.f, 0.f, 0.f, 0.f);  // channels 8cg..8cg+3
        float4 accHi = make_float4(0.f, 0.f, 0.f, 0.f);  // channels 8cg+4..8cg+7
        #pragma unroll
        for (int r = 0; r < 4; r++) {
            const char* br = featb + rowv[r];
            const uint4 v0 = ldg128cs(br + col.x);   // 8 channels, col 0
            const uint4 v1 = ldg128cs(br + col.y);
            const uint4 v2 = ldg128cs(br + col.z);
            const uint4 v3 = ldg128cs(br + col.w);

            __half2 rs0 = __hmul2(aw0, u2h(v0.x));
            __half2 rs1 = __hmul2(aw0, u2h(v0.y));
            __half2 rs2 = __hmul2(aw0, u2h(v0.z));
            __half2 rs3 = __hmul2(aw0, u2h(v0.w));
            rs0 = __hfma2(aw1, u2h(v1.x), rs0);
            rs1 = __hfma2(aw1, u2h(v1.y), rs1);
            rs2 = __hfma2(aw1, u2h(v1.z), rs2);
            rs3 = __hfma2(aw1, u2h(v1.w), rs3);
            rs0 = __hfma2(aw2, u2h(v2.x), rs0);
            rs1 = __hfma2(aw2, u2h(v2.y), rs1);
            rs2 = __hfma2(aw2, u2h(v2.z), rs2);
            rs3 = __hfma2(aw2, u2h(v2.w), rs3);
            rs0 = __hfma2(aw3, u2h(v3.x), rs0);
            rs1 = __hfma2(aw3, u2h(v3.y), rs1);
            rs2 = __hfma2(aw3, u2h(v3.z), rs2);
            rs3 = __hfma2(aw3, u2h(v3.w), rs3);

            const float2 f0 = __half22float2(rs0);
            const float2 f1 = __half22float2(rs1);
            const float2 f2 = __half22float2(rs2);
            const float2 f3 = __half22float2(rs3);
            accLo.x += ayv[r] * f0.x;
            accLo.y += ayv[r] * f0.y;
            accLo.z += ayv[r] * f1.x;
            accLo.w += ayv[r] * f1.y;
            accHi.x += ayv[r] * f2.x;
            accHi.y += ayv[r] * f2.y;
            accHi.z += ayv[r] * f3.x;
            accHi.w += ayv[r] * f3.y;
        }

        // conflict-free STS.128: slots cg and 33+cg (stride 66 float4 per bin)
        s_out4[bsub * 66 + cg]      = accLo;   // float4 index 2cg
        s_out4[bsub * 66 + 33 + cg] = accHi;   // float4 index 2cg+1
    }

    __syncthreads();

    // ---------------- Phase 3: grouped output store ----------------
    // channel c, bin j: float4 f = c/4 (= 2cg + hi), slot = (f&1)?33+(f>>1):(f>>1)
    float* o = out + (size_t)n * CH * NBINS + bin0;
    const float* s_outf = (const float*)s_out4;
    #pragma unroll
    for (int i = tid; i < CH * 7; i += 224) {
        const int c = i / 7;
        const int j = i - c * 7;
        const int f = c >> 2;
        const int slot = (f & 1) ? (33 + (f >> 1)) : (f >> 1);
        o[c * NBINS + j] = s_outf[j * 264 + slot * 4 + (c & 3)];
    }
}

extern "C" void kernel_launch(void* const* d_in, const int* in_sizes, int n_in,
                              void* d_out, int out_size)
{
    const float* bottom_data  = (const float*)d_in[0];  // (2,256,96,96)
    const float* bottom_rois  = (const float*)d_in[1];  // (512,5)
    const float* bottom_trans = (const float*)d_in[2];  // (512,2,7,7)
    float* out = (float*)d_out;                         // (512,256,7,7)

    {
        dim3 tb(32, 8);
        dim3 tg(FHW / 32, CH / 32, BATCH);
        nchw_to_nhwc_half_kernel<<<tg, tb>>>(bottom_data);
    }
    {
        dim3 pg(7, N_ROIS);
        dpsroi_pool_kernel<<<pg, 224>>>(bottom_rois, bottom_trans, out);
    }
}